// round 8
// baseline (speedup 1.0000x reference)
#include <cuda_runtime.h>

#define NB      2
#define CC      512
#define SS      256
#define CTILE   4
#define DCHUNK  16
#define NCHUNK  (CC / DCHUNK)     // 32
#define THREADS 256
#define WARPS   8
#define NSTAGE  3

#define CHUNK_BYTES  (DCHUNK * SS * 4)           // 16384 per tensor per chunk
#define STAGE_FLOATS (DCHUNK * SS)               // 4096

// smem (floats):
//  ks: [3][DCHUNK][SS] = 12288 floats
//  vs: [3][DCHUNK][SS] = 12288 floats
//  rw: [WARPS][8][33]  =  2112 floats
//  mbar: full[3] + empty[3], 8B each
#define VS_OFF      (NSTAGE * STAGE_FLOATS)
#define RW_OFF      (2 * NSTAGE * STAGE_FLOATS)
#define MBAR_OFF    (RW_OFF + WARPS * 8 * 33)    // float idx, even -> 8B aligned
#define SMEM_BYTES  ((MBAR_OFF + 16) * 4)        // 106816 B (2 CTAs fit per SM)

typedef unsigned long long ull;

__device__ __forceinline__ ull add2(ull a, ull b) {
    ull c; asm("add.rn.f32x2 %0, %1, %2;" : "=l"(c) : "l"(a), "l"(b)); return c;
}
__device__ __forceinline__ ull mul2(ull a, ull b) {
    ull c; asm("mul.rn.f32x2 %0, %1, %2;" : "=l"(c) : "l"(a), "l"(b)); return c;
}
__device__ __forceinline__ ull fma2(ull a, ull b, ull c) {
    ull d; asm("fma.rn.f32x2 %0, %1, %2, %3;" : "=l"(d) : "l"(a), "l"(b), "l"(c)); return d;
}
__device__ __forceinline__ ull pack2(float x, float y) {
    ull r; asm("mov.b64 %0, {%1, %2};" : "=l"(r) : "f"(x), "f"(y)); return r;
}
__device__ __forceinline__ ull dup2(float x) { return pack2(x, x); }
__device__ __forceinline__ float2 unpack2f(ull a) {
    float2 r; asm("mov.b64 {%0, %1}, %2;" : "=f"(r.x), "=f"(r.y) : "l"(a)); return r;
}

// ---- TMA bulk staging + mbarrier ring ----
__device__ __forceinline__ void bulk_g2s(void* sdst, const void* gsrc,
                                         unsigned bytes, unsigned mbar) {
    unsigned d = (unsigned)__cvta_generic_to_shared(sdst);
    asm volatile(
        "cp.async.bulk.shared::cluster.global.mbarrier::complete_tx::bytes "
        "[%0], [%1], %2, [%3];"
        :: "r"(d), "l"(gsrc), "r"(bytes), "r"(mbar) : "memory");
}
__device__ __forceinline__ void mbar_init(unsigned mbar, unsigned count) {
    asm volatile("mbarrier.init.shared.b64 [%0], %1;" :: "r"(mbar), "r"(count) : "memory");
}
__device__ __forceinline__ void mbar_expect_tx(unsigned mbar, unsigned bytes) {
    asm volatile("mbarrier.arrive.expect_tx.shared.b64 _, [%0], %1;"
                 :: "r"(mbar), "r"(bytes) : "memory");
}
__device__ __forceinline__ void mbar_arrive(unsigned mbar) {
    asm volatile("mbarrier.arrive.shared.b64 _, [%0];" :: "r"(mbar) : "memory");
}
__device__ __forceinline__ void mbar_wait(unsigned mbar, unsigned parity) {
    asm volatile(
        "{\n\t"
        ".reg .pred P;\n\t"
        "W%=:\n\t"
        "mbarrier.try_wait.parity.acquire.cta.shared::cta.b64 P, [%0], %1, 0x989680;\n\t"
        "@!P bra W%=;\n\t"
        "}"
        :: "r"(mbar), "r"(parity) : "memory");
}

extern __shared__ __align__(16) float smem[];

__global__ void __launch_bounds__(THREADS, 2)
laplace_attn_kernel(const float* __restrict__ q,
                    const float* __restrict__ k,
                    const float* __restrict__ v,
                    float* __restrict__ out)
{
    float* ks  = smem;                           // [3][DCHUNK][SS]
    float* vs  = smem + VS_OFF;                  // [3][DCHUNK][SS]
    float* rwb = smem + RW_OFF;                  // [WARPS][8][33]
    const unsigned mb_full  = (unsigned)__cvta_generic_to_shared(smem + MBAR_OFF);
    const unsigned mb_empty = mb_full + 8u * NSTAGE;

    const int tid = threadIdx.x;
    const int w   = tid >> 5;                    // warp 0..7 = d-split
    const int l   = tid & 31;
    const int ds  = w;                           // 2 d's of each 16-d chunk
    const int n   = blockIdx.x / (CC / CTILE);
    const int ct  = blockIdx.x % (CC / CTILE);
    const int c0  = ct * CTILE;                  // block's 4 rows

    float* rw = rwb + w * (8 * 33);

    const float* kbase = k + (size_t)n * CC * SS;
    const float* vbase = v + (size_t)n * CC * SS;

    // init barriers + fill all 3 stages (chunks 0..2)
    if (tid == 0) {
#pragma unroll
        for (int s = 0; s < NSTAGE; s++) {
            mbar_init(mb_full  + 8u * s, 1);
            mbar_init(mb_empty + 8u * s, WARPS);
        }
        asm volatile("fence.proxy.async.shared::cta;" ::: "memory");
#pragma unroll
        for (int s = 0; s < NSTAGE; s++) {
            mbar_expect_tx(mb_full + 8u * s, 2 * CHUNK_BYTES);
            bulk_g2s(ks + s * STAGE_FLOATS, kbase + (size_t)s * STAGE_FLOATS,
                     CHUNK_BYTES, mb_full + 8u * s);
            bulk_g2s(vs + s * STAGE_FLOATS, vbase + (size_t)s * STAGE_FLOATS,
                     CHUNK_BYTES, mb_full + 8u * s);
        }
    }

    // Lane's s-slice: {4l..4l+3} and {128+4l..128+4l+3} (lane-contiguous
    // float4 blocks -> every smem LDS.128 is bank-conflict-free).
    ull nq[4][4];
#pragma unroll
    for (int r = 0; r < 4; r++) {
        const float* qp = q + ((size_t)n * CC + c0 + r) * SS;
        float4 a = *(const float4*)(qp + 4 * l);
        float4 b = *(const float4*)(qp + 128 + 4 * l);
        nq[r][0] = pack2(-a.x, -a.y);
        nq[r][1] = pack2(-a.z, -a.w);
        nq[r][2] = pack2(-b.x, -b.y);
        nq[r][3] = pack2(-b.z, -b.w);
    }

    ull acc[4][4];
#pragma unroll
    for (int r = 0; r < 4; r++)
#pragma unroll
        for (int j = 0; j < 4; j++) acc[r][j] = 0ULL;

    // lane's row = l>>3 (lanes 8r..8r+7 service row r; entry = 2r + (l>>2 & 1))
    float m_own = -1e30f;
    float lsum_own = 0.f;

    __syncthreads();   // barrier init visible before any wait

    int st = 0;        // ring stage = ch % 3
    int rnd = 0;       // ring round = ch / 3

#pragma unroll 1
    for (int ch = 0; ch < NCHUNK; ch++) {
        mbar_wait(mb_full + 8u * st, (unsigned)(rnd & 1));

        const float* kc = ks + st * STAGE_FLOATS;
        const float* vc = vs + st * STAGE_FLOATS;

        // ---- distance partials: 2 d's x 4 rows; FADD |.| modifiers ----
#pragma unroll
        for (int dl = 0; dl < 2; dl++) {
            const int d = ds * 2 + dl;
            const ulonglong2 ka = *(const ulonglong2*)(kc + d * SS + 4 * l);
            const ulonglong2 kb = *(const ulonglong2*)(kc + d * SS + 128 + 4 * l);
#pragma unroll
            for (int r = 0; r < 4; r++) {
                const float2 f0 = unpack2f(add2(ka.x, nq[r][0]));
                const float2 f1 = unpack2f(add2(ka.y, nq[r][1]));
                const float2 f2 = unpack2f(add2(kb.x, nq[r][2]));
                const float2 f3 = unpack2f(add2(kb.y, nq[r][3]));
                const float s0 = fabsf(f0.x) + fabsf(f0.y);
                const float s1 = fabsf(f1.x) + fabsf(f1.y);
                const float s2 = fabsf(f2.x) + fabsf(f2.y);
                const float s3 = fabsf(f3.x) + fabsf(f3.y);
                rw[(r * 2 + dl) * 33 + l] = (s0 + s1) + (s2 + s3);
            }
        }
        __syncwarp();

        // ---- transpose-reduce: 4 lanes per entry (8 entries) ----
        const int e   = l >> 2;                  // entry = row*2 + dl
        const int qtr = l & 3;
        const float* rr = rw + e * 33 + qtr * 8;
        float s0 = rr[0] + rr[1], s1 = rr[2] + rr[3];
        float s2 = rr[4] + rr[5], s3 = rr[6] + rr[7];
        float dist = (s0 + s1) + (s2 + s3);
        dist += __shfl_xor_sync(0xffffffffu, dist, 1);
        dist += __shfl_xor_sync(0xffffffffu, dist, 2);
        const float wv = -0.5f * dist;           // logits = -dist/SCALE, SCALE=2

        // ---- per-warp online softmax (row segment = this warp's 2 d's) ----
        float cm = fmaxf(wv, __shfl_xor_sync(0xffffffffu, wv, 4));
        if (__any_sync(0xffffffffu, cm > m_own)) {
            const float mnew = fmaxf(m_own, cm);
            const float corr = __expf(m_own - mnew);
            m_own = mnew;
            lsum_own *= corr;
#pragma unroll
            for (int r = 0; r < 4; r++) {
                const float cr = __shfl_sync(0xffffffffu, corr, r * 8);
                const ull c2 = dup2(cr);
#pragma unroll
                for (int j = 0; j < 4; j++) acc[r][j] = mul2(acc[r][j], c2);
            }
        }
        const float pv = __expf(wv - m_own);
        lsum_own += pv + __shfl_xor_sync(0xffffffffu, pv, 4);

        // ---- P @ V: packed FMA, p broadcast via shfl ----
#pragma unroll
        for (int dl = 0; dl < 2; dl++) {
            const int d = ds * 2 + dl;
            const ulonglong2 va = *(const ulonglong2*)(vc + d * SS + 4 * l);
            const ulonglong2 vb = *(const ulonglong2*)(vc + d * SS + 128 + 4 * l);
#pragma unroll
            for (int r = 0; r < 4; r++) {
                const float pj = __shfl_sync(0xffffffffu, pv, r * 8 + dl * 4);
                const ull p2 = dup2(pj);
                acc[r][0] = fma2(p2, va.x, acc[r][0]);
                acc[r][1] = fma2(p2, va.y, acc[r][1]);
                acc[r][2] = fma2(p2, vb.x, acc[r][2]);
                acc[r][3] = fma2(p2, vb.y, acc[r][3]);
            }
        }

        if (l == 0) mbar_arrive(mb_empty + 8u * st);

        // producer: refill stage st with chunk ch+3 once all warps released it
        if (tid == 0 && ch + NSTAGE < NCHUNK) {
            mbar_wait(mb_empty + 8u * st, (unsigned)(rnd & 1));
            mbar_expect_tx(mb_full + 8u * st, 2 * CHUNK_BYTES);
            bulk_g2s(ks + st * STAGE_FLOATS,
                     kbase + (size_t)(ch + NSTAGE) * STAGE_FLOATS,
                     CHUNK_BYTES, mb_full + 8u * st);
            bulk_g2s(vs + st * STAGE_FLOATS,
                     vbase + (size_t)(ch + NSTAGE) * STAGE_FLOATS,
                     CHUNK_BYTES, mb_full + 8u * st);
        }

        if (++st == NSTAGE) { st = 0; rnd++; }
    }

    __syncthreads();   // all warps done with all stages; smem reusable

    // ================= epilogue: merge the 8 d-split segments =================
    float* accbuf = smem;                        // [4 rows][8 splits][256]
    float* stats  = smem + 4 * 8 * 256;          // [4 rows][8 splits][2]

#pragma unroll
    for (int r = 0; r < 4; r++) {
        float* dst = accbuf + (r * 8 + ds) * 256;
        *(ulonglong2*)(dst + 4 * l)       = make_ulonglong2(acc[r][0], acc[r][1]);
        *(ulonglong2*)(dst + 128 + 4 * l) = make_ulonglong2(acc[r][2], acc[r][3]);
    }
    if ((l & 7) == 0) {
        const int row = l >> 3;
        stats[(row * 8 + ds) * 2 + 0] = m_own;
        stats[(row * 8 + ds) * 2 + 1] = lsum_own;
    }
    __syncthreads();

    {
        const int row  = w >> 1;
        const int half = w & 1;
        const int sb   = half * 128 + l * 4;

        float M = -1e30f;
#pragma unroll
        for (int i = 0; i < 8; i++) M = fmaxf(M, stats[(row * 8 + i) * 2]);

        float L = 0.f;
        ull o0 = 0ULL, o1 = 0ULL;
#pragma unroll
        for (int i = 0; i < 8; i++) {
            const float sc = __expf(stats[(row * 8 + i) * 2] - M);
            L += stats[(row * 8 + i) * 2 + 1] * sc;
            const ulonglong2 a = *(const ulonglong2*)(accbuf + (row * 8 + i) * 256 + sb);
            const ull s2 = dup2(sc);
            o0 = fma2(s2, a.x, o0);
            o1 = fma2(s2, a.y, o1);
        }
        const ull i2 = dup2(1.f / L);
        o0 = mul2(o0, i2);
        o1 = mul2(o1, i2);

        const int c = c0 + row;
        *(ulonglong2*)(out + ((size_t)n * CC + c) * SS + sb) = make_ulonglong2(o0, o1);
    }
}

extern "C" void kernel_launch(void* const* d_in, const int* in_sizes, int n_in,
                              void* d_out, int out_size) {
    const float* q = (const float*)d_in[0];
    const float* k = (const float*)d_in[1];
    const float* v = (const float*)d_in[2];
    float* out = (float*)d_out;

    cudaFuncSetAttribute(laplace_attn_kernel,
                         cudaFuncAttributeMaxDynamicSharedMemorySize, SMEM_BYTES);

    laplace_attn_kernel<<<NB * (CC / CTILE), THREADS, SMEM_BYTES>>>(q, k, v, out);
}

// round 10
// speedup vs baseline: 1.2453x; 1.2453x over previous
#include <cuda_runtime.h>

#define NB      2
#define CC      512
#define SS      256
#define DCHUNK  32
#define NKCH    16
#define THREADS 512
#define WARPS   16

#define CHUNK_BYTES  (DCHUNK * SS * 4)           // 32768 (one tensor)
#define STAGE_FLOATS (DCHUNK * SS)               // 8192

// smem (floats):
//  kbuf: [2][8192] = 16384
//  vbuf: [2][8192] = 16384
//  rw:   [16][16][33] = 8448
//  logits: [8][516] = 4128
//  mtmp: 32
//  mbar: kfull[2], vfull[2] (8B each)
#define KBUF_OFF  0
#define VBUF_OFF  16384
#define RW_OFF    32768
#define LG_OFF    (RW_OFF + WARPS * 16 * 33)     // 41216
#define LSTRIDE   516
#define MT_OFF    (LG_OFF + 8 * LSTRIDE)         // 45344
#define MBAR_OFF  (MT_OFF + 32)                  // 45376 (even -> 8B aligned)
#define SMEM_BYTES ((MBAR_OFF + 8) * 4)          // 181536 B

typedef unsigned long long ull;

__device__ __forceinline__ ull add2(ull a, ull b) {
    ull c; asm("add.rn.f32x2 %0, %1, %2;" : "=l"(c) : "l"(a), "l"(b)); return c;
}
__device__ __forceinline__ ull fma2(ull a, ull b, ull c) {
    ull d; asm("fma.rn.f32x2 %0, %1, %2, %3;" : "=l"(d) : "l"(a), "l"(b), "l"(c)); return d;
}
__device__ __forceinline__ ull pack2(float x, float y) {
    ull r; asm("mov.b64 %0, {%1, %2};" : "=l"(r) : "f"(x), "f"(y)); return r;
}
__device__ __forceinline__ ull dup2(float x) { return pack2(x, x); }
__device__ __forceinline__ float2 unpack2f(ull a) {
    float2 r; asm("mov.b64 {%0, %1}, %2;" : "=f"(r.x), "=f"(r.y) : "l"(a)); return r;
}

__device__ __forceinline__ void bulk_g2s(void* sdst, const void* gsrc,
                                         unsigned bytes, unsigned mbar) {
    unsigned d = (unsigned)__cvta_generic_to_shared(sdst);
    asm volatile(
        "cp.async.bulk.shared::cluster.global.mbarrier::complete_tx::bytes "
        "[%0], [%1], %2, [%3];"
        :: "r"(d), "l"(gsrc), "r"(bytes), "r"(mbar) : "memory");
}
__device__ __forceinline__ void mbar_init(unsigned mbar, unsigned count) {
    asm volatile("mbarrier.init.shared.b64 [%0], %1;" :: "r"(mbar), "r"(count) : "memory");
}
__device__ __forceinline__ void mbar_expect_tx(unsigned mbar, unsigned bytes) {
    asm volatile("mbarrier.arrive.expect_tx.shared.b64 _, [%0], %1;"
                 :: "r"(mbar), "r"(bytes) : "memory");
}
__device__ __forceinline__ void mbar_wait(unsigned mbar, unsigned parity) {
    asm volatile(
        "{\n\t"
        ".reg .pred P;\n\t"
        "W%=:\n\t"
        "mbarrier.try_wait.parity.acquire.cta.shared::cta.b64 P, [%0], %1, 0x989680;\n\t"
        "@!P bra W%=;\n\t"
        "}"
        :: "r"(mbar), "r"(parity) : "memory");
}

extern __shared__ __align__(16) float smem[];

__global__ void __launch_bounds__(THREADS, 1)
laplace_attn_kernel(const float* __restrict__ q,
                    const float* __restrict__ k,
                    const float* __restrict__ v,
                    float* __restrict__ out)
{
    float* kbuf   = smem + KBUF_OFF;             // [2][DCHUNK][SS]
    float* vbuf   = smem + VBUF_OFF;             // [2][DCHUNK][SS]
    float* rwb    = smem + RW_OFF;               // [WARPS][16][33]
    float* logits = smem + LG_OFF;               // [8][516]
    float* mtmp   = smem + MT_OFF;               // [8][2] max; +16: [8][2] sum
    const unsigned mb_k = (unsigned)__cvta_generic_to_shared(smem + MBAR_OFF);
    const unsigned mb_v = mb_k + 16u;

    const int tid = threadIdx.x;
    const int w   = tid >> 5;
    const int l   = tid & 31;
    const int g   = w & 1;                       // row-group (4 rows each)
    const int ds  = w >> 1;                      // d-split 0..7 (4 d's per chunk)
    const int n   = blockIdx.x / (CC / 8);
    const int ct  = blockIdx.x % (CC / 8);
    const int c0  = ct * 8 + g * 4;

    float* rw = rwb + w * (16 * 33);

    const float* kbase = k + (size_t)n * CC * SS;
    const float* vbase = v + (size_t)n * CC * SS;

    // prologue: init 4 barriers; stage k chunk 0, and PREFETCH v chunks 0,1
    if (tid == 0) {
        mbar_init(mb_k,      1);
        mbar_init(mb_k + 8,  1);
        mbar_init(mb_v,      1);
        mbar_init(mb_v + 8,  1);
        asm volatile("fence.proxy.async.shared::cta;" ::: "memory");
        mbar_expect_tx(mb_k, CHUNK_BYTES);
        bulk_g2s(kbuf, kbase, CHUNK_BYTES, mb_k);
        mbar_expect_tx(mb_v, CHUNK_BYTES);
        bulk_g2s(vbuf, vbase, CHUNK_BYTES, mb_v);
        mbar_expect_tx(mb_v + 8, CHUNK_BYTES);
        bulk_g2s(vbuf + STAGE_FLOATS, vbase + STAGE_FLOATS, CHUNK_BYTES, mb_v + 8);
    }

    // Lane's s-slice: {4l..4l+3} and {128+4l..128+4l+3} (conflict-free LDS.128)
    ull nq[4][4];
#pragma unroll
    for (int r = 0; r < 4; r++) {
        const float* qp = q + ((size_t)n * CC + c0 + r) * SS;
        float4 a = *(const float4*)(qp + 4 * l);
        float4 b = *(const float4*)(qp + 128 + 4 * l);
        nq[r][0] = pack2(-a.x, -a.y);
        nq[r][1] = pack2(-a.z, -a.w);
        nq[r][2] = pack2(-b.x, -b.y);
        nq[r][3] = pack2(-b.z, -b.w);
    }

    __syncthreads();   // barrier init visible before any wait

    // ================= pass 1: distances -> raw logits =================
#pragma unroll 1
    for (int ch = 0; ch < NKCH; ch++) {
        const int p = ch & 1;

        // stage next k chunk into other buffer (released by ch-1's syncthreads)
        if (ch + 1 < NKCH && tid == 0) {
            const unsigned mb = mb_k + 8u * (1 - p);
            mbar_expect_tx(mb, CHUNK_BYTES);
            bulk_g2s(kbuf + (1 - p) * STAGE_FLOATS,
                     kbase + (size_t)(ch + 1) * STAGE_FLOATS, CHUNK_BYTES, mb);
        }
        mbar_wait(mb_k + 8u * p, (unsigned)((ch >> 1) & 1));

        const float* kc = kbuf + p * STAGE_FLOATS;

#pragma unroll
        for (int dl = 0; dl < 4; dl++) {
            const int d = ds * 4 + dl;
            const ulonglong2 ka = *(const ulonglong2*)(kc + d * SS + 4 * l);
            const ulonglong2 kb = *(const ulonglong2*)(kc + d * SS + 128 + 4 * l);
#pragma unroll
            for (int r = 0; r < 4; r++) {
                const float2 f0 = unpack2f(add2(ka.x, nq[r][0]));
                const float2 f1 = unpack2f(add2(ka.y, nq[r][1]));
                const float2 f2 = unpack2f(add2(kb.x, nq[r][2]));
                const float2 f3 = unpack2f(add2(kb.y, nq[r][3]));
                const float s0 = fabsf(f0.x) + fabsf(f0.y);
                const float s1 = fabsf(f1.x) + fabsf(f1.y);
                const float s2 = fabsf(f2.x) + fabsf(f2.y);
                const float s3 = fabsf(f3.x) + fabsf(f3.y);
                rw[(r * 4 + dl) * 33 + l] = (s0 + s1) + (s2 + s3);
            }
        }
        __syncwarp();

        // transpose-reduce -> logit store (no softmax here)
        const int e = l & 15;
        const int h = l >> 4;
        const float* rr = rw + e * 33 + h * 16;
        float s0 = 0.f, s1 = 0.f, s2 = 0.f, s3 = 0.f;
#pragma unroll
        for (int j = 0; j < 16; j += 4) {
            s0 += rr[j + 0]; s1 += rr[j + 1];
            s2 += rr[j + 2]; s3 += rr[j + 3];
        }
        float dist = (s0 + s1) + (s2 + s3);
        dist += __shfl_xor_sync(0xffffffffu, dist, 16);
        if (l < 16)
            logits[(g * 4 + (l >> 2)) * LSTRIDE + ch * DCHUNK + ds * 4 + (l & 3)]
                = -0.5f * dist;                  // logits = -dist/SCALE, SCALE=2

        __syncthreads();                         // releases k buffer p
    }

    // ================= exact softmax per row (in place -> P) =================
    {
        const int row  = w >> 1;
        const int half = w & 1;
        float* lrow = logits + row * LSTRIDE + half * 256;
        float4 a = *(const float4*)(lrow + 4 * l);
        float4 b = *(const float4*)(lrow + 128 + 4 * l);

        float mx = fmaxf(fmaxf(fmaxf(a.x, a.y), fmaxf(a.z, a.w)),
                         fmaxf(fmaxf(b.x, b.y), fmaxf(b.z, b.w)));
#pragma unroll
        for (int off = 16; off; off >>= 1)
            mx = fmaxf(mx, __shfl_xor_sync(0xffffffffu, mx, off));
        if (l == 0) mtmp[row * 2 + half] = mx;
        __syncthreads();
        const float m = fmaxf(mtmp[row * 2], mtmp[row * 2 + 1]);

        float e0 = __expf(a.x - m), e1 = __expf(a.y - m);
        float e2 = __expf(a.z - m), e3 = __expf(a.w - m);
        float e4 = __expf(b.x - m), e5 = __expf(b.y - m);
        float e6 = __expf(b.z - m), e7 = __expf(b.w - m);
        float s = ((e0 + e1) + (e2 + e3)) + ((e4 + e5) + (e6 + e7));
#pragma unroll
        for (int off = 16; off; off >>= 1)
            s += __shfl_xor_sync(0xffffffffu, s, off);
        if (l == 0) mtmp[16 + row * 2 + half] = s;
        __syncthreads();
        const float inv = 1.f / (mtmp[16 + row * 2] + mtmp[16 + row * 2 + 1]);

        float4 pa, pb;
        pa.x = e0 * inv; pa.y = e1 * inv; pa.z = e2 * inv; pa.w = e3 * inv;
        pb.x = e4 * inv; pb.y = e5 * inv; pb.z = e6 * inv; pb.w = e7 * inv;
        *(float4*)(lrow + 4 * l)       = pa;     // logits now hold normalized P
        *(float4*)(lrow + 128 + 4 * l) = pb;
    }
    __syncthreads();                             // P visible to all warps

    // ================= pass 2: out = P @ V =================
    ull acc[4][4];
#pragma unroll
    for (int r = 0; r < 4; r++)
#pragma unroll
        for (int j = 0; j < 4; j++) acc[r][j] = 0ULL;

#pragma unroll 1
    for (int j = 0; j < NKCH; j++) {
        const int p = j & 1;
        mbar_wait(mb_v + 8u * p, (unsigned)((j >> 1) & 1));

        const float* vc = vbuf + p * STAGE_FLOATS;

        // P for this warp: rows g*4..g*4+3, cols j*32+ds*4..+3 (broadcast LDS.128)
        float pj[4][4];
#pragma unroll
        for (int r = 0; r < 4; r++) {
            const float4 pr =
                *(const float4*)(logits + (g * 4 + r) * LSTRIDE + j * DCHUNK + ds * 4);
            pj[r][0] = pr.x; pj[r][1] = pr.y; pj[r][2] = pr.z; pj[r][3] = pr.w;
        }

#pragma unroll
        for (int dl = 0; dl < 4; dl++) {
            const int d = ds * 4 + dl;
            const ulonglong2 va = *(const ulonglong2*)(vc + d * SS + 4 * l);
            const ulonglong2 vb = *(const ulonglong2*)(vc + d * SS + 128 + 4 * l);
#pragma unroll
            for (int r = 0; r < 4; r++) {
                const ull p2 = dup2(pj[r][dl]);
                acc[r][0] = fma2(p2, va.x, acc[r][0]);
                acc[r][1] = fma2(p2, va.y, acc[r][1]);
                acc[r][2] = fma2(p2, vb.x, acc[r][2]);
                acc[r][3] = fma2(p2, vb.y, acc[r][3]);
            }
        }

        __syncthreads();                         // releases v buffer p

        // refill buffer p with v chunk j+2 (safe: just released by all)
        if (tid == 0 && j + 2 < NKCH) {
            const unsigned mb = mb_v + 8u * p;
            mbar_expect_tx(mb, CHUNK_BYTES);
            bulk_g2s(vbuf + p * STAGE_FLOATS,
                     vbase + (size_t)(j + 2) * STAGE_FLOATS, CHUNK_BYTES, mb);
        }
    }

    // ================= epilogue: pure sum over the 8 d-splits =================
    float* accbuf = smem;                        // [8 rows][8 splits][256] = 64KB
#pragma unroll
    for (int r = 0; r < 4; r++) {
        float* dst = accbuf + ((g * 4 + r) * 8 + ds) * 256;
        *(ulonglong2*)(dst + 4 * l)       = make_ulonglong2(acc[r][0], acc[r][1]);
        *(ulonglong2*)(dst + 128 + 4 * l) = make_ulonglong2(acc[r][2], acc[r][3]);
    }
    __syncthreads();

    {
        const int row  = w >> 1;
        const int half = w & 1;
        const int sb   = half * 128 + l * 4;

        ull o0 = 0ULL, o1 = 0ULL;
#pragma unroll
        for (int i = 0; i < 8; i++) {
            const ulonglong2 a = *(const ulonglong2*)(accbuf + (row * 8 + i) * 256 + sb);
            o0 = add2(o0, a.x);
            o1 = add2(o1, a.y);
        }
        const int c = ct * 8 + row;
        *(ulonglong2*)(out + ((size_t)n * CC + c) * SS + sb) = make_ulonglong2(o0, o1);
    }
}

extern "C" void kernel_launch(void* const* d_in, const int* in_sizes, int n_in,
                              void* d_out, int out_size) {
    const float* q = (const float*)d_in[0];
    const float* k = (const float*)d_in[1];
    const float* v = (const float*)d_in[2];
    float* out = (float*)d_out;

    cudaFuncSetAttribute(laplace_attn_kernel,
                         cudaFuncAttributeMaxDynamicSharedMemorySize, SMEM_BYTES);

    laplace_attn_kernel<<<NB * (CC / 8), THREADS, SMEM_BYTES>>>(q, k, v, out);
}

// round 11
// speedup vs baseline: 1.3487x; 1.0830x over previous
#include <cuda_runtime.h>

#define NB      2
#define CC      512
#define SS      256
#define DCHUNK  64
#define NKCH    8
#define THREADS 512
#define WARPS   16

#define CHUNK_BYTES  (DCHUNK * SS * 4)           // 65536 (one tensor)
#define STAGE_FLOATS (DCHUNK * SS)               // 16384

// smem (floats):
//  buf (k, later v): [2][16384] = 32768
//  rw:   [16][16][33] = 8448
//  logits: [8][516] = 4128
//  mtmp: 32
//  mbar: full[2] (8B each)
#define BUF_OFF   0
#define RW_OFF    32768
#define LG_OFF    (RW_OFF + WARPS * 16 * 33)     // 41216
#define LSTRIDE   516
#define MT_OFF    (LG_OFF + 8 * LSTRIDE)         // 45344
#define MBAR_OFF  (MT_OFF + 32)                  // 45376 (even -> 8B aligned)
#define SMEM_BYTES ((MBAR_OFF + 8) * 4)          // 181536 B

typedef unsigned long long ull;

__device__ __forceinline__ ull add2(ull a, ull b) {
    ull c; asm("add.rn.f32x2 %0, %1, %2;" : "=l"(c) : "l"(a), "l"(b)); return c;
}
__device__ __forceinline__ ull fma2(ull a, ull b, ull c) {
    ull d; asm("fma.rn.f32x2 %0, %1, %2, %3;" : "=l"(d) : "l"(a), "l"(b), "l"(c)); return d;
}
__device__ __forceinline__ ull pack2(float x, float y) {
    ull r; asm("mov.b64 %0, {%1, %2};" : "=l"(r) : "f"(x), "f"(y)); return r;
}
__device__ __forceinline__ ull dup2(float x) { return pack2(x, x); }
__device__ __forceinline__ float2 unpack2f(ull a) {
    float2 r; asm("mov.b64 {%0, %1}, %2;" : "=f"(r.x), "=f"(r.y) : "l"(a)); return r;
}

__device__ __forceinline__ void bulk_g2s(void* sdst, const void* gsrc,
                                         unsigned bytes, unsigned mbar) {
    unsigned d = (unsigned)__cvta_generic_to_shared(sdst);
    asm volatile(
        "cp.async.bulk.shared::cluster.global.mbarrier::complete_tx::bytes "
        "[%0], [%1], %2, [%3];"
        :: "r"(d), "l"(gsrc), "r"(bytes), "r"(mbar) : "memory");
}
__device__ __forceinline__ void mbar_init(unsigned mbar, unsigned count) {
    asm volatile("mbarrier.init.shared.b64 [%0], %1;" :: "r"(mbar), "r"(count) : "memory");
}
__device__ __forceinline__ void mbar_expect_tx(unsigned mbar, unsigned bytes) {
    asm volatile("mbarrier.arrive.expect_tx.shared.b64 _, [%0], %1;"
                 :: "r"(mbar), "r"(bytes) : "memory");
}
__device__ __forceinline__ void mbar_wait(unsigned mbar, unsigned parity) {
    asm volatile(
        "{\n\t"
        ".reg .pred P;\n\t"
        "W%=:\n\t"
        "mbarrier.try_wait.parity.acquire.cta.shared::cta.b64 P, [%0], %1, 0x989680;\n\t"
        "@!P bra W%=;\n\t"
        "}"
        :: "r"(mbar), "r"(parity) : "memory");
}

extern __shared__ __align__(16) float smem[];

__global__ void __launch_bounds__(THREADS, 1)
laplace_attn_kernel(const float* __restrict__ q,
                    const float* __restrict__ k,
                    const float* __restrict__ v,
                    float* __restrict__ out)
{
    float* buf    = smem + BUF_OFF;              // [2][DCHUNK][SS]  k then v
    float* rwb    = smem + RW_OFF;               // [WARPS][16][33]
    float* logits = smem + LG_OFF;               // [8][516]
    float* mtmp   = smem + MT_OFF;               // [8][2] max; +16: [8][2] sum
    const unsigned mb = (unsigned)__cvta_generic_to_shared(smem + MBAR_OFF);

    const int tid = threadIdx.x;
    const int w   = tid >> 5;
    const int l   = tid & 31;
    const int g   = w & 1;                       // row-group (4 rows each)
    const int ds  = w >> 1;                      // d-split 0..7 (8 d's per 64-chunk)
    const int n   = blockIdx.x / (CC / 8);
    const int ct  = blockIdx.x % (CC / 8);
    const int c0  = ct * 8 + g * 4;

    float* rw = rwb + w * (16 * 33);

    const float* kbase = k + (size_t)n * CC * SS;
    const float* vbase = v + (size_t)n * CC * SS;

    // prologue: init barriers; stage k chunk 0 into buffer 0
    if (tid == 0) {
        mbar_init(mb,     1);
        mbar_init(mb + 8, 1);
        asm volatile("fence.proxy.async.shared::cta;" ::: "memory");
        mbar_expect_tx(mb, CHUNK_BYTES);
        bulk_g2s(buf, kbase, CHUNK_BYTES, mb);
    }

    // Lane's s-slice: {4l..4l+3} and {128+4l..128+4l+3} (conflict-free LDS.128)
    ull nq[4][4];
#pragma unroll
    for (int r = 0; r < 4; r++) {
        const float* qp = q + ((size_t)n * CC + c0 + r) * SS;
        float4 a = *(const float4*)(qp + 4 * l);
        float4 b = *(const float4*)(qp + 128 + 4 * l);
        nq[r][0] = pack2(-a.x, -a.y);
        nq[r][1] = pack2(-a.z, -a.w);
        nq[r][2] = pack2(-b.x, -b.y);
        nq[r][3] = pack2(-b.z, -b.w);
    }

    __syncthreads();   // barrier init visible before any wait

    // ================= pass 1: distances -> raw logits =================
#pragma unroll 1
    for (int ch = 0; ch < NKCH; ch++) {
        const int p = ch & 1;

        // stage next k chunk into other buffer (released by ch-1's syncthreads)
        if (ch + 1 < NKCH && tid == 0) {
            mbar_expect_tx(mb + 8u * (1 - p), CHUNK_BYTES);
            bulk_g2s(buf + (1 - p) * STAGE_FLOATS,
                     kbase + (size_t)(ch + 1) * STAGE_FLOATS, CHUNK_BYTES,
                     mb + 8u * (1 - p));
        }
        mbar_wait(mb + 8u * p, (unsigned)((ch >> 1) & 1));

        const float* kc = buf + p * STAGE_FLOATS;

#pragma unroll
        for (int grp = 0; grp < 2; grp++) {
            // ---- distance partials: 4 d's x 4 rows ----
#pragma unroll
            for (int dl = 0; dl < 4; dl++) {
                const int d = ds * 8 + grp * 4 + dl;
                const ulonglong2 ka = *(const ulonglong2*)(kc + d * SS + 4 * l);
                const ulonglong2 kb = *(const ulonglong2*)(kc + d * SS + 128 + 4 * l);
#pragma unroll
                for (int r = 0; r < 4; r++) {
                    const float2 f0 = unpack2f(add2(ka.x, nq[r][0]));
                    const float2 f1 = unpack2f(add2(ka.y, nq[r][1]));
                    const float2 f2 = unpack2f(add2(kb.x, nq[r][2]));
                    const float2 f3 = unpack2f(add2(kb.y, nq[r][3]));
                    const float s0 = fabsf(f0.x) + fabsf(f0.y);
                    const float s1 = fabsf(f1.x) + fabsf(f1.y);
                    const float s2 = fabsf(f2.x) + fabsf(f2.y);
                    const float s3 = fabsf(f3.x) + fabsf(f3.y);
                    rw[(r * 4 + dl) * 33 + l] = (s0 + s1) + (s2 + s3);
                }
            }
            __syncwarp();

            // ---- transpose-reduce -> logit store ----
            const int e = l & 15;
            const int h = l >> 4;
            const float* rr = rw + e * 33 + h * 16;
            float s0 = 0.f, s1 = 0.f, s2 = 0.f, s3 = 0.f;
#pragma unroll
            for (int j = 0; j < 16; j += 4) {
                s0 += rr[j + 0]; s1 += rr[j + 1];
                s2 += rr[j + 2]; s3 += rr[j + 3];
            }
            float dist = (s0 + s1) + (s2 + s3);
            dist += __shfl_xor_sync(0xffffffffu, dist, 16);
            if (l < 16)
                logits[(g * 4 + (l >> 2)) * LSTRIDE
                       + ch * DCHUNK + ds * 8 + grp * 4 + (l & 3)]
                    = -0.5f * dist;              // logits = -dist/SCALE, SCALE=2
            __syncwarp();                        // rw reused by next group
        }

        __syncthreads();                         // releases k buffer p
    }

    // v prefetch: both buffers provably free after the final pass-1 barrier.
    // Loads overlap the softmax phase below.
    if (tid == 0) {
        mbar_expect_tx(mb, CHUNK_BYTES);
        bulk_g2s(buf, vbase, CHUNK_BYTES, mb);
        mbar_expect_tx(mb + 8, CHUNK_BYTES);
        bulk_g2s(buf + STAGE_FLOATS, vbase + STAGE_FLOATS, CHUNK_BYTES, mb + 8);
    }

    // ================= exact softmax per row (in place -> P) =================
    {
        const int row  = w >> 1;
        const int half = w & 1;
        float* lrow = logits + row * LSTRIDE + half * 256;
        float4 a = *(const float4*)(lrow + 4 * l);
        float4 b = *(const float4*)(lrow + 128 + 4 * l);

        float mx = fmaxf(fmaxf(fmaxf(a.x, a.y), fmaxf(a.z, a.w)),
                         fmaxf(fmaxf(b.x, b.y), fmaxf(b.z, b.w)));
#pragma unroll
        for (int off = 16; off; off >>= 1)
            mx = fmaxf(mx, __shfl_xor_sync(0xffffffffu, mx, off));
        if (l == 0) mtmp[row * 2 + half] = mx;
        __syncthreads();
        const float m = fmaxf(mtmp[row * 2], mtmp[row * 2 + 1]);

        float e0 = __expf(a.x - m), e1 = __expf(a.y - m);
        float e2 = __expf(a.z - m), e3 = __expf(a.w - m);
        float e4 = __expf(b.x - m), e5 = __expf(b.y - m);
        float e6 = __expf(b.z - m), e7 = __expf(b.w - m);
        float s = ((e0 + e1) + (e2 + e3)) + ((e4 + e5) + (e6 + e7));
#pragma unroll
        for (int off = 16; off; off >>= 1)
            s += __shfl_xor_sync(0xffffffffu, s, off);
        if (l == 0) mtmp[16 + row * 2 + half] = s;
        __syncthreads();
        const float inv = 1.f / (mtmp[16 + row * 2] + mtmp[16 + row * 2 + 1]);

        float4 pa, pb;
        pa.x = e0 * inv; pa.y = e1 * inv; pa.z = e2 * inv; pa.w = e3 * inv;
        pb.x = e4 * inv; pb.y = e5 * inv; pb.z = e6 * inv; pb.w = e7 * inv;
        *(float4*)(lrow + 4 * l)       = pa;     // logits now hold normalized P
        *(float4*)(lrow + 128 + 4 * l) = pb;
    }
    __syncthreads();                             // P visible to all warps

    // ================= pass 2: out = P @ V =================
    ull acc[4][4];
#pragma unroll
    for (int r = 0; r < 4; r++)
#pragma unroll
        for (int j = 0; j < 4; j++) acc[r][j] = 0ULL;

#pragma unroll 1
    for (int j = 0; j < NKCH; j++) {
        const int p = j & 1;
        // k used each buffer's barrier 4x (even) -> fresh-equivalent parity
        mbar_wait(mb + 8u * p, (unsigned)((j >> 1) & 1));

        const float* vc = buf + p * STAGE_FLOATS;

#pragma unroll
        for (int grp = 0; grp < 2; grp++) {
            // P for this warp: rows g*4..+3, cols j*64+ds*8+grp*4..+3
            float pj[4][4];
#pragma unroll
            for (int r = 0; r < 4; r++) {
                const float4 pr = *(const float4*)(logits + (g * 4 + r) * LSTRIDE
                                                   + j * DCHUNK + ds * 8 + grp * 4);
                pj[r][0] = pr.x; pj[r][1] = pr.y; pj[r][2] = pr.z; pj[r][3] = pr.w;
            }
#pragma unroll
            for (int dl = 0; dl < 4; dl++) {
                const int d = ds * 8 + grp * 4 + dl;
                const ulonglong2 va = *(const ulonglong2*)(vc + d * SS + 4 * l);
                const ulonglong2 vb = *(const ulonglong2*)(vc + d * SS + 128 + 4 * l);
#pragma unroll
                for (int r = 0; r < 4; r++) {
                    const ull p2 = dup2(pj[r][dl]);
                    acc[r][0] = fma2(p2, va.x, acc[r][0]);
                    acc[r][1] = fma2(p2, va.y, acc[r][1]);
                    acc[r][2] = fma2(p2, vb.x, acc[r][2]);
                    acc[r][3] = fma2(p2, vb.y, acc[r][3]);
                }
            }
        }

        __syncthreads();                         // releases v buffer p

        // refill buffer p with v chunk j+2 (just released by all warps)
        if (tid == 0 && j + 2 < NKCH) {
            mbar_expect_tx(mb + 8u * p, CHUNK_BYTES);
            bulk_g2s(buf + p * STAGE_FLOATS,
                     vbase + (size_t)(j + 2) * STAGE_FLOATS, CHUNK_BYTES,
                     mb + 8u * p);
        }
    }

    // ================= epilogue: pure sum over the 8 d-splits =================
    float* accbuf = smem;                        // [8 rows][8 splits][256] = 64KB
#pragma unroll
    for (int r = 0; r < 4; r++) {
        float* dst = accbuf + ((g * 4 + r) * 8 + ds) * 256;
        *(ulonglong2*)(dst + 4 * l)       = make_ulonglong2(acc[r][0], acc[r][1]);
        *(ulonglong2*)(dst + 128 + 4 * l) = make_ulonglong2(acc[r][2], acc[r][3]);
    }
    __syncthreads();

    {
        const int row  = w >> 1;
        const int half = w & 1;
        const int sb   = half * 128 + l * 4;

        ull o0 = 0ULL, o1 = 0ULL;
#pragma unroll
        for (int i = 0; i < 8; i++) {
            const ulonglong2 a = *(const ulonglong2*)(accbuf + (row * 8 + i) * 256 + sb);
            o0 = add2(o0, a.x);
            o1 = add2(o1, a.y);
        }
        const int c = ct * 8 + row;
        *(ulonglong2*)(out + ((size_t)n * CC + c) * SS + sb) = make_ulonglong2(o0, o1);
    }
}

extern "C" void kernel_launch(void* const* d_in, const int* in_sizes, int n_in,
                              void* d_out, int out_size) {
    const float* q = (const float*)d_in[0];
    const float* k = (const float*)d_in[1];
    const float* v = (const float*)d_in[2];
    float* out = (float*)d_out;

    cudaFuncSetAttribute(laplace_attn_kernel,
                         cudaFuncAttributeMaxDynamicSharedMemorySize, SMEM_BYTES);

    laplace_attn_kernel<<<NB * (CC / 8), THREADS, SMEM_BYTES>>>(q, k, v, out);
}